// round 5
// baseline (speedup 1.0000x reference)
#include <cuda_runtime.h>

// GlottalFlowTable — fixed shapes: B=32, S=524288, HOP=256, L=100, frames=2048
//
// R5: persistent threads + software pipeline. R4 showed L1TEX-bound at 72%
// density (floor ~23us) with ptxas re-serializing the gather batch (regs=32).
// Here each thread handles ~14 chunks of 8 samples; the NEXT chunk's wp
// float4 loads are issued before the CURRENT chunk's gathers/math, hiding
// the ~600-cycle DRAM latency under L1 gather work. __launch_bounds__(256,4)
// gives ptxas a 64-reg budget so prefetch + gather batch stay live.

constexpr int B      = 32;
constexpr int S      = 524288;
constexpr int HOP    = 256;
constexpr int L      = 100;
constexpr int FRAMES = S / HOP;    // 2048
constexpr int TROWS  = FRAMES + 1; // 2049
constexpr int TOTAL8 = (B * S) / 8;   // 2,097,152 chunks of 8 samples
constexpr int NBLK   = 148 * 4;       // persistent grid
constexpr int NTHR   = 256;
constexpr int STRIDE = NBLK * NTHR;   // 151,552 threads

struct Chunk { float w[8]; };

__device__ __forceinline__ void load_chunk(const float* __restrict__ wp,
                                           int c, Chunk& ck)
{
    const float4* wv = reinterpret_cast<const float4*>(wp) + (size_t)c * 2;
    float4 a = __ldg(wv);
    float4 b = __ldg(wv + 1);
    ck.w[0]=a.x; ck.w[1]=a.y; ck.w[2]=a.z; ck.w[3]=a.w;
    ck.w[4]=b.x; ck.w[5]=b.y; ck.w[6]=b.z; ck.w[7]=b.w;
}

__device__ __forceinline__ void process_chunk(const Chunk& ck, int c,
                                              const float* __restrict__ tables,
                                              float* __restrict__ out)
{
    // c indexes 8-sample groups globally; 65536 groups per batch row.
    int b  = c >> 16;
    int s  = (c & 0xFFFF) << 3;            // sample index within batch row
    int f  = s >> 8;                       // frame (8 | 256: no straddle)
    int t  = s & (HOP - 1);

    const float* rowF = tables + (size_t)(b * TROWS + f) * L;
    const float* rowC = rowF + L;

    int   fi[8], fj[8];
    float p[8];
#pragma unroll
    for (int k = 0; k < 8; ++k) {
        float idx_raw = ck.w[k] * (float)L;
        int   v       = (int)idx_raw;              // trunc toward zero
        v             = max(0, min(v, L - 1));     // clip like reference
        fi[k]         = v;
        p[k]          = idx_raw - (float)v;
        int   u       = v + 1;
        fj[k]         = (u == L) ? 0 : u;          // padded col L == col 0
    }

    float loF[8], hiF[8], loC[8], hiC[8];
#pragma unroll
    for (int k = 0; k < 8; ++k) loF[k] = __ldg(rowF + fi[k]);
#pragma unroll
    for (int k = 0; k < 8; ++k) hiF[k] = __ldg(rowF + fj[k]);
#pragma unroll
    for (int k = 0; k < 8; ++k) loC[k] = __ldg(rowC + fi[k]);
#pragma unroll
    for (int k = 0; k < 8; ++k) hiC[k] = __ldg(rowC + fj[k]);

    float r[8];
#pragma unroll
    for (int k = 0; k < 8; ++k) {
        float vF = fmaf(p[k], hiF[k] - loF[k], loF[k]);
        float vC = fmaf(p[k], hiC[k] - loC[k], loC[k]);
        float p2 = (float)(t + k) * (1.0f / (float)HOP);
        r[k] = fmaf(p2, vC - vF, vF);
    }

    float4* ov = reinterpret_cast<float4*>(out) + (size_t)c * 2;
    ov[0] = make_float4(r[0], r[1], r[2], r[3]);
    ov[1] = make_float4(r[4], r[5], r[6], r[7]);
}

__global__ __launch_bounds__(NTHR, 4)
void glottal_flow_kernel(const float* __restrict__ wp,
                         const float* __restrict__ tables,
                         float* __restrict__ out)
{
    int c = blockIdx.x * NTHR + threadIdx.x;

    if (c >= TOTAL8) return;

    Chunk cur, nxt;
    load_chunk(wp, c, cur);

    // Pipelined main loop: prefetch chunk c+STRIDE while processing c.
    while (c + STRIDE < TOTAL8) {
        load_chunk(wp, c + STRIDE, nxt);
        process_chunk(cur, c, tables, out);
        cur = nxt;
        c += STRIDE;
    }
    process_chunk(cur, c, tables, out);
}

extern "C" void kernel_launch(void* const* d_in, const int* in_sizes, int n_in,
                              void* d_out, int out_size)
{
    const float* wp     = (const float*)d_in[0];
    const float* tables = (const float*)d_in[1];
    float*       out    = (float*)d_out;

    glottal_flow_kernel<<<NBLK, NTHR>>>(wp, tables, out);
}

// round 6
// speedup vs baseline: 1.1641x; 1.1641x over previous
#include <cuda_runtime.h>

// GlottalFlowTable — fixed shapes: B=32, S=524288, HOP=256, L=100, frames=2048
//
// R6: the workload is at the random-gather hardware wall (~140 cyc per
// 256-sample warp-chunk; smem/shuffle/scratch alternatives all compute and/or
// measure worse). This round consolidates the empirically best pieces:
//  - R1's per-sample gather->math interleave (30.4us; front-batched gathers in
//    R4/R5 were 31.2-31.5 — large MLP front-batches inflate L1tex queueing)
//  - R4's float4 I/O (8 samples/thread, 2x LDG.128 + 2x STG.128 streaming)
//  - __ldcs / __stcs streaming hints on wp/out so the 26MB table stays
//    L2-resident for the gathers.

constexpr int B      = 32;
constexpr int S      = 524288;
constexpr int HOP    = 256;
constexpr int L      = 100;
constexpr int FRAMES = S / HOP;    // 2048
constexpr int TROWS  = FRAMES + 1; // 2049

__global__ __launch_bounds__(256)
void glottal_flow_kernel(const float* __restrict__ wp,
                         const float* __restrict__ tables,
                         float* __restrict__ out)
{
    int c = blockIdx.x * 256 + threadIdx.x;   // 8-sample chunk index
    int b = c >> 16;                          // 65536 chunks per batch row
    int s = (c & 0xFFFF) << 3;                // sample within batch row
    int f = s >> 8;                           // frame (8 | 256: no straddle)
    int t = s & (HOP - 1);

    const float4* wv = reinterpret_cast<const float4*>(wp) + (size_t)c * 2;
    float4 w0 = __ldcs(wv);                   // streaming: evict-first
    float4 w1 = __ldcs(wv + 1);

    const float* rowF = tables + (size_t)(b * TROWS + f) * L;
    const float* rowC = rowF + L;

    float w[8] = {w0.x, w0.y, w0.z, w0.w, w1.x, w1.y, w1.z, w1.w};
    float r[8];

    // Per-sample interleaved gather + math (R1 shape — best measured).
#pragma unroll
    for (int k = 0; k < 8; ++k) {
        float idx_raw = w[k] * (float)L;
        int   fi      = (int)idx_raw;              // trunc toward zero
        fi            = max(0, min(fi, L - 1));    // clip like reference
        float p       = idx_raw - (float)fi;
        int   fj      = fi + 1;
        if (fj == L) fj = 0;                       // padded col L == col 0

        float loF = __ldg(rowF + fi);
        float hiF = __ldg(rowF + fj);
        float loC = __ldg(rowC + fi);
        float hiC = __ldg(rowC + fj);

        float vF = fmaf(p, hiF - loF, loF);
        float vC = fmaf(p, hiC - loC, loC);
        float p2 = (float)(t + k) * (1.0f / (float)HOP);
        r[k] = fmaf(p2, vC - vF, vF);
    }

    float4* ov = reinterpret_cast<float4*>(out) + (size_t)c * 2;
    __stcs(ov,     make_float4(r[0], r[1], r[2], r[3]));  // streaming store
    __stcs(ov + 1, make_float4(r[4], r[5], r[6], r[7]));
}

extern "C" void kernel_launch(void* const* d_in, const int* in_sizes, int n_in,
                              void* d_out, int out_size)
{
    const float* wp     = (const float*)d_in[0];
    const float* tables = (const float*)d_in[1];
    float*       out    = (float*)d_out;

    constexpr int total8 = (B * S) / 8;            // 2,097,152 chunks
    glottal_flow_kernel<<<total8 / 256, 256>>>(wp, tables, out);
}

// round 7
// speedup vs baseline: 1.1856x; 1.0185x over previous
#include <cuda_runtime.h>

// GlottalFlowTable — fixed shapes: B=32, S=524288, HOP=256, L=100, frames=2048
//
// R7: consolidation at the gather wall. Across R1-R6, every alternative gather
// unit (shuffle, smem quad, front-batched MLP, persistent+prefetch) measured
// equal or worse than the plain 4-samples/thread scalar-LDG kernel (R1,
// 30.4us kernel — the fastest). Wavefront accounting shows the bilinear
// 4-gather is L1TEX-floor-bound and re-packings are wavefront-invariant.
// This round = exact R1 structure + R6's streaming hints (__ldcs on wp,
// __stcs on out), which cut DRAM traffic ~16% at zero cost and keep the
// 26MB table L2-resident.

constexpr int B      = 32;
constexpr int S      = 524288;
constexpr int HOP    = 256;
constexpr int L      = 100;
constexpr int FRAMES = S / HOP;    // 2048
constexpr int TROWS  = FRAMES + 1; // 2049
constexpr int S4     = S / 4;      // 131072 float4 per batch row

__global__ __launch_bounds__(256)
void glottal_flow_kernel(const float* __restrict__ wp,
                         const float* __restrict__ tables,
                         float* __restrict__ out)
{
    int i4 = blockIdx.x * 256 + threadIdx.x;   // global float4 index
    int b  = i4 >> 17;                         // / S4 (131072)
    int s  = (i4 & (S4 - 1)) << 2;             // sample index within batch row
    int f  = s >> 8;                           // frame (HOP = 256)
    int t  = s & (HOP - 1);                    // position within frame

    float4 w = __ldcs(reinterpret_cast<const float4*>(wp) + i4);  // streaming

    const float* rowF = tables + (size_t)(b * TROWS + f) * L; // floor frame row
    const float* rowC = rowF + L;                              // ceil frame row

    float wk[4] = {w.x, w.y, w.z, w.w};
    float r[4];

#pragma unroll
    for (int k = 0; k < 4; ++k) {
        float idx_raw = wk[k] * (float)L;
        int   fi      = (int)idx_raw;              // trunc toward zero (data >= 0)
        fi            = max(0, min(fi, L - 1));    // clip like reference
        float p       = idx_raw - (float)fi;
        int   fj      = fi + 1;
        if (fj == L) fj = 0;                       // padded column L == column 0

        float loF = __ldg(rowF + fi);
        float hiF = __ldg(rowF + fj);
        float loC = __ldg(rowC + fi);
        float hiC = __ldg(rowC + fj);

        float vF = fmaf(p, hiF - loF, loF);        // phase lerp, floor frame
        float vC = fmaf(p, hiC - loC, loC);        // phase lerp, ceil frame
        float p2 = (float)(t + k) * (1.0f / (float)HOP);
        r[k] = fmaf(p2, vC - vF, vF);              // frame lerp
    }

    __stcs(reinterpret_cast<float4*>(out) + i4,    // streaming store
           make_float4(r[0], r[1], r[2], r[3]));
}

extern "C" void kernel_launch(void* const* d_in, const int* in_sizes, int n_in,
                              void* d_out, int out_size)
{
    const float* wp     = (const float*)d_in[0];
    const float* tables = (const float*)d_in[1];
    float*       out    = (float*)d_out;

    constexpr int total4 = (B * S) / 4;            // 4,194,304 float4 work items
    glottal_flow_kernel<<<total4 / 256, 256>>>(wp, tables, out);
}